// round 15
// baseline (speedup 1.0000x reference)
#include <cuda_runtime.h>

#define NTOT       1572864      // 3 * 32 * 128 * 128 scores
#define NQ         393216       // NTOT / 4
#define W_DIM      128
#define H_DIM      128
#define CH_STRIDE  524288       // 32*128*128 (per-channel stride)
#define PRE_N      2000
#define POST_N     300
#define CAND_CAP   4096
#define NMS_T      0.7f
#define MASK_ROWS  512          // precomputed mask rows (fallback covers the rest)
#define HBINS      262144       // 2^18 coarse bins
#define BIN_SHIFT  14           // key >> 14 -> bin

// ---------------- scratch (device globals; zero-initialized at load) -------
__device__ unsigned g_hist[HBINS];
__device__ unsigned g_thresh;
__device__ unsigned g_candCount;
__device__ unsigned long long g_cand[CAND_CAP];
__device__ int g_topIdx[PRE_N];

__device__ float4 g_boxA[PRE_N];   // x1, y1, z1, vol
__device__ float4 g_boxBp[PRE_N];  // x2+1, y2+1, z2+1, (unused)
__device__ float g_bx2[PRE_N], g_by2[PRE_N], g_bz2[PRE_N];   // raw, for output
__device__ float g_sc[PRE_N];

__device__ unsigned g_supp32[64];                 // initial suppression bits
__device__ unsigned long long g_mask[MASK_ROWS * 32]; // NMS bitmask rows (i<512)

__device__ __forceinline__ unsigned mapKey(float f) {
    unsigned b = __float_as_uint(f);
    return b ^ ((b & 0x80000000u) ? 0xFFFFFFFFu : 0x80000000u);
}

// ---------------- 1) coarse 18-bit histogram --------------------------------
__global__ void k_hist(const float4* __restrict__ sc) {
    int t = blockIdx.x * blockDim.x + threadIdx.x;   // 0..NQ-1 exactly
    float4 v = __ldg(&sc[t]);
    atomicAdd(&g_hist[mapKey(v.x) >> BIN_SHIFT], 1u);
    atomicAdd(&g_hist[mapKey(v.y) >> BIN_SHIFT], 1u);
    atomicAdd(&g_hist[mapKey(v.z) >> BIN_SHIFT], 1u);
    atomicAdd(&g_hist[mapKey(v.w) >> BIN_SHIFT], 1u);
}

// ---------------- 2) find boundary bin (coalesced, warp-segmented) ----------
__global__ void k_scan() {
    __shared__ unsigned warpTot[32];
    __shared__ unsigned suffAbove[32];
    __shared__ int boundWarp;
    int t = threadIdx.x;             // 1024 threads = 32 warps
    int w = t >> 5, l = t & 31;
    if (t == 0) { g_candCount = 0u; boundWarp = -1; }
    int seg = w * 8192;              // warp w owns bins [seg, seg+8192)
    unsigned s = 0;
    #pragma unroll 16
    for (int i = 0; i < 256; i++) s += g_hist[seg + i * 32 + l];   // coalesced
    #pragma unroll
    for (int d = 16; d > 0; d >>= 1) s += __shfl_down_sync(0xFFFFFFFFu, s, d);
    if (l == 0) warpTot[w] = s;
    __syncthreads();
    if (w == 0) {
        unsigned tot = warpTot[l];
        unsigned suf = tot;
        #pragma unroll
        for (int d = 1; d < 32; d <<= 1) {
            unsigned v = __shfl_down_sync(0xFFFFFFFFu, suf, d);
            if (l + d < 32) suf += v;
        }
        unsigned above = suf - tot;
        if (above < PRE_N && suf >= PRE_N) { boundWarp = l; suffAbove[l] = above; }
    }
    __syncthreads();
    if (w == boundWarp) {
        unsigned running = suffAbove[w];
        for (int c = 255; c >= 0; c--) {
            unsigned h = g_hist[seg + c * 32 + l];
            unsigned suf = h;                 // suffix over lanes >= l
            #pragma unroll
            for (int d = 1; d < 32; d <<= 1) {
                unsigned v = __shfl_down_sync(0xFFFFFFFFu, suf, d);
                if (l + d < 32) suf += v;
            }
            unsigned bal = __ballot_sync(0xFFFFFFFFu, running + suf >= PRE_N);
            if (bal) {
                if (l == 0) {
                    int lb = 31 - __clz(bal);          // highest qualifying lane
                    unsigned bin = (unsigned)(seg + c * 32 + lb);
                    g_thresh = bin << BIN_SHIFT;
                }
                break;
            }
            running += __shfl_sync(0xFFFFFFFFu, suf, 0);   // whole-chunk total
        }
    }
}

// ---------------- 3) collect candidates (transposed idx = pos*3 + a) --------
__global__ void k_collect(const float4* __restrict__ sc) {
    unsigned T = g_thresh;
    int t = blockIdx.x * blockDim.x + threadIdx.x;
    float4 v = __ldg(&sc[t]);
    int base = 4 * t;
    int a = base / CH_STRIDE;            // all 4 elements share the channel
    int pos = base - a * CH_STRIDE;
    unsigned k0 = mapKey(v.x), k1 = mapKey(v.y), k2 = mapKey(v.z), k3 = mapKey(v.w);
    if (k0 >= T) { unsigned p = atomicAdd(&g_candCount, 1u); if (p < CAND_CAP) g_cand[p] = ((unsigned long long)(~k0) << 32) | (unsigned)((pos + 0) * 3 + a); }
    if (k1 >= T) { unsigned p = atomicAdd(&g_candCount, 1u); if (p < CAND_CAP) g_cand[p] = ((unsigned long long)(~k1) << 32) | (unsigned)((pos + 1) * 3 + a); }
    if (k2 >= T) { unsigned p = atomicAdd(&g_candCount, 1u); if (p < CAND_CAP) g_cand[p] = ((unsigned long long)(~k2) << 32) | (unsigned)((pos + 2) * 3 + a); }
    if (k3 >= T) { unsigned p = atomicAdd(&g_candCount, 1u); if (p < CAND_CAP) g_cand[p] = ((unsigned long long)(~k3) << 32) | (unsigned)((pos + 3) * 3 + a); }
}

// ---------------- 4) rank-and-scatter: 128 blocks, warp-per-4-keys ----------
__global__ void k_rank() {
    __shared__ unsigned long long sKeys[CAND_CAP];
    int tid = threadIdx.x;
    int cc = (int)g_candCount; if (cc > CAND_CAP) cc = CAND_CAP;
    for (int i = tid; i < cc; i += 256) sKeys[i] = g_cand[i];
    __syncthreads();
    int w = tid >> 5, l = tid & 31;
    int kbase = blockIdx.x * 32 + w * 4;      // this warp owns keys kbase..+3
    if (kbase >= cc) return;
    unsigned long long k0 = sKeys[kbase];
    unsigned long long k1 = (kbase + 1 < cc) ? sKeys[kbase + 1] : 0xFFFFFFFFFFFFFFFFULL;
    unsigned long long k2 = (kbase + 2 < cc) ? sKeys[kbase + 2] : 0xFFFFFFFFFFFFFFFFULL;
    unsigned long long k3 = (kbase + 3 < cc) ? sKeys[kbase + 3] : 0xFFFFFFFFFFFFFFFFULL;
    int r0 = 0, r1 = 0, r2 = 0, r3 = 0;
    for (int j = l; j < cc; j += 32) {
        unsigned long long kj = sKeys[j];
        r0 += (kj < k0); r1 += (kj < k1); r2 += (kj < k2); r3 += (kj < k3);
    }
    #pragma unroll
    for (int d = 16; d > 0; d >>= 1) {
        r0 += __shfl_down_sync(0xFFFFFFFFu, r0, d);
        r1 += __shfl_down_sync(0xFFFFFFFFu, r1, d);
        r2 += __shfl_down_sync(0xFFFFFFFFu, r2, d);
        r3 += __shfl_down_sync(0xFFFFFFFFu, r3, d);
    }
    if (l == 0) {
        if (r0 < PRE_N)                    g_topIdx[r0] = (int)(k0 & 0xFFFFFFFFu);
        if (kbase + 1 < cc && r1 < PRE_N)  g_topIdx[r1] = (int)(k1 & 0xFFFFFFFFu);
        if (kbase + 2 < cc && r2 < PRE_N)  g_topIdx[r2] = (int)(k2 & 0xFFFFFFFFu);
        if (kbase + 3 < cc && r3 < PRE_N)  g_topIdx[r3] = (int)(k3 & 0xFFFFFFFFu);
    }
}

// ---------------- 5) box decode + validity ----------------------------------
__global__ void k_transform(const float* __restrict__ sc,
                            const float* __restrict__ dl,
                            const float* __restrict__ imi,
                            const float* __restrict__ anc) {
    int r = blockIdx.x * blockDim.x + threadIdx.x;    // 8x256 covers 2048
    bool valid = false;
    if (r < PRE_N) {
        int idx = g_topIdx[r];            // transposed flat index
        int a   = idx % 3;
        int pos = idx / 3;
        int wl  = pos % W_DIM;
        int hl  = (pos / W_DIM) % H_DIM;
        int sl  = pos / (W_DIM * H_DIM);
        float shx = wl * 4.0f, shy = hl * 4.0f, shz = sl * 4.0f;
        float ax1 = anc[a*6+0] + shx, ay1 = anc[a*6+1] + shy, az1 = anc[a*6+2] + shz;
        float ax2 = anc[a*6+3] + shx, ay2 = anc[a*6+4] + shy, az2 = anc[a*6+5] + shz;

        const float* db = dl + (size_t)(6 * a) * CH_STRIDE + pos;
        float d0 = db[0];
        float d1 = db[(size_t)CH_STRIDE];
        float d2 = db[(size_t)2 * CH_STRIDE];
        float d3 = db[(size_t)3 * CH_STRIDE];
        float d4 = db[(size_t)4 * CH_STRIDE];
        float d5 = db[(size_t)5 * CH_STRIDE];

        float w_ = ax2 - ax1 + 1.0f, h_ = ay2 - ay1 + 1.0f, dd = az2 - az1 + 1.0f;
        float cx = ax1 + 0.5f * w_, cy = ay1 + 0.5f * h_, cz = az1 + 0.5f * dd;
        float pcx = d0 * w_ + cx, pcy = d1 * h_ + cy, pcz = d2 * dd + cz;
        float pw = expf(d3) * w_, ph = expf(d4) * h_, pd = expf(d5) * dd;

        float slices = imi[0], height = imi[1], width = imi[2], scale = imi[3];
        float x1 = fminf(fmaxf(pcx - 0.5f * pw, 0.0f), width  - 1.0f);
        float y1 = fminf(fmaxf(pcy - 0.5f * ph, 0.0f), height - 1.0f);
        float z1 = fminf(fmaxf(pcz - 0.5f * pd, 0.0f), slices - 1.0f);
        float x2 = fminf(fmaxf(pcx + 0.5f * pw - 1.0f, 0.0f), width  - 1.0f);
        float y2 = fminf(fmaxf(pcy + 0.5f * ph - 1.0f, 0.0f), height - 1.0f);
        float z2 = fminf(fmaxf(pcz + 0.5f * pd - 1.0f, 0.0f), slices - 1.0f);

        float vol = (x2 - x1 + 1.0f) * (y2 - y1 + 1.0f) * (z2 - z1 + 1.0f);
        g_boxA[r]  = make_float4(x1, y1, z1, vol);
        g_boxBp[r] = make_float4(x2 + 1.0f, y2 + 1.0f, z2 + 1.0f, 0.0f);
        g_bx2[r] = x2; g_by2[r] = y2; g_bz2[r] = z2;
        g_sc[r]  = sc[(size_t)a * CH_STRIDE + pos];

        float ss = x2 - x1 + 1.0f;
        float xc = x1 + ss * 0.5f, yc = y1 + ss * 0.5f, zc = z1 + ss * 0.5f;
        valid = (ss >= 8.0f * scale) && (xc < width) && (yc < height) && (zc < slices);
    }
    unsigned suppressed = __ballot_sync(0xFFFFFFFFu, !valid);
    if ((threadIdx.x & 31) == 0) g_supp32[r >> 5] = suppressed;
}

// ---------------- 6) IoU bitmask for rows i < MASK_ROWS + hist re-zero ------
__global__ void k_mask() {
    int by = blockIdx.y, bx = blockIdx.x;   // grid (32, 8)
    int t = threadIdx.x;                    // 64 threads
    // re-zero histogram: 256 blocks x 64 thr x 16 = 262144 (coalesced)
    {
        int gt = (by * 32 + bx) * 64 + t;
        #pragma unroll
        for (int k = 0; k < 16; k++) g_hist[gt + k * 16384] = 0u;
    }
    if (bx < by) return;                    // j < i words are never non-zero
    __shared__ float4 sA[64], sB[64];
    int jbase = bx * 64;
    int j = jbase + t;
    if (j < PRE_N) { sA[t] = g_boxA[j]; sB[t] = g_boxBp[j]; }
    __syncthreads();
    int i = by * 64 + t;                    // i < 512 always
    float4 A  = g_boxA[i];
    float4 Bp = g_boxBp[i];
    unsigned long long m = 0ULL;
    int jmax = PRE_N - jbase; if (jmax > 64) jmax = 64;
    for (int c = 0; c < jmax; c++) {
        int jg = jbase + c;
        if (jg <= i) continue;              // only diagonal tiles hit this
        float4 jA = sA[c], jB = sB[c];
        float iw = fmaxf(fminf(Bp.x, jB.x) - fmaxf(A.x, jA.x), 0.0f);
        float ih = fmaxf(fminf(Bp.y, jB.y) - fmaxf(A.y, jA.y), 0.0f);
        float id = fmaxf(fminf(Bp.z, jB.z) - fmaxf(A.z, jA.z), 0.0f);
        float inter = iw * ih * id;
        if (inter > NMS_T * (A.w + jA.w - inter)) m |= (1ULL << c);
    }
    g_mask[(size_t)i * 32 + bx] = m;
}

// ---------------- 7) greedy reduce (smem rows + fallback) + output ----------
__global__ void k_reduceout(float* __restrict__ out, int out_size) {
    extern __shared__ unsigned long long rowsSm[];    // MASK_ROWS * 32 (128 KB)
    __shared__ int sKeep[POST_N];
    __shared__ int sKept;
    int t = threadIdx.x;                              // 1024 threads
    for (int w = t; w < MASK_ROWS * 32; w += 1024) rowsSm[w] = g_mask[w];
    __syncthreads();
    if (t < 32) {
        int lane = t;
        unsigned long long remv =
            ((unsigned long long)g_supp32[2 * lane + 1] << 32) | g_supp32[2 * lane];
        int kept = 0;
        int curWI = 0;
        unsigned long long curw = __shfl_sync(0xFFFFFFFFu, remv, 0);
        for (int i = 0; i < PRE_N; i++) {
            int wi = i >> 6;
            if (wi != curWI) {                       // word crossing: re-broadcast
                curw = __shfl_sync(0xFFFFFFFFu, remv, wi);
                curWI = wi;
            }
            if (!((curw >> (i & 63)) & 1ULL)) {      // keep i
                unsigned long long row;
                if (i < MASK_ROWS) {
                    row = rowsSm[i * 32 + lane];
                } else {
                    // fallback: compute row i on the fly (lane covers 64 j's)
                    row = 0ULL;
                    float4 A  = __ldg(&g_boxA[i]);
                    float4 Bp = __ldg(&g_boxBp[i]);
                    int j0 = lane * 64;
                    int cmax = PRE_N - j0; if (cmax > 64) cmax = 64;
                    for (int c = 0; c < cmax; c++) {
                        int j = j0 + c;
                        if (j <= i) continue;
                        float4 jA = __ldg(&g_boxA[j]);
                        float4 jB = __ldg(&g_boxBp[j]);
                        float iw = fmaxf(fminf(Bp.x, jB.x) - fmaxf(A.x, jA.x), 0.0f);
                        float ih = fmaxf(fminf(Bp.y, jB.y) - fmaxf(A.y, jA.y), 0.0f);
                        float id = fmaxf(fminf(Bp.z, jB.z) - fmaxf(A.z, jA.z), 0.0f);
                        float inter = iw * ih * id;
                        if (inter > NMS_T * (A.w + jA.w - inter)) row |= (1ULL << c);
                    }
                }
                remv |= row;
                curw = __shfl_sync(0xFFFFFFFFu, remv, wi);  // refresh after OR
                if (lane == 0) sKeep[kept] = i;
                kept++;
                if (kept == POST_N) break;
            }
        }
        if (lane == 0) sKept = kept;
    }
    __syncthreads();
    int kept = sKept;
    for (int s = t; s < POST_N; s += 1024) {
        float b0, b1, b2, b3, b4, b5, scv, kidx, vld;
        if (s < kept) {
            int i = sKeep[s];
            float4 A = g_boxA[i];
            b0 = A.x; b1 = A.y; b2 = A.z;
            b3 = g_bx2[i]; b4 = g_by2[i]; b5 = g_bz2[i];
            scv = g_sc[i]; kidx = (float)g_topIdx[i]; vld = 1.0f;
        } else {
            b0 = b1 = b2 = b3 = b4 = b5 = 0.0f;
            scv = 0.0f; kidx = -1.0f; vld = 0.0f;
        }
        int base = s * 7;
        out[base + 0] = 0.0f;
        out[base + 1] = b0; out[base + 2] = b1; out[base + 3] = b2;
        out[base + 4] = b3; out[base + 5] = b4; out[base + 6] = b5;
        if (out_size >= POST_N * 7 + POST_N) out[POST_N * 7 + s] = scv;
        if (out_size >= POST_N * 8 + POST_N) out[POST_N * 8 + s] = kidx;
        if (out_size >= POST_N * 9 + POST_N) out[POST_N * 9 + s] = vld;
    }
}

// ---------------- launcher --------------------------------------------------
extern "C" void kernel_launch(void* const* d_in, const int* in_sizes, int n_in,
                              void* d_out, int out_size) {
    const float*  sc  = (const float*)d_in[0];
    const float4* sc4 = (const float4*)d_in[0];
    const float*  dl  = (const float*)d_in[1];
    const float*  imi = (const float*)d_in[2];
    const float*  anc = (const float*)d_in[3];
    float* out = (float*)d_out;

    cudaFuncSetAttribute(k_reduceout, cudaFuncAttributeMaxDynamicSharedMemorySize,
                         MASK_ROWS * 32 * (int)sizeof(unsigned long long));

    k_hist     <<<NQ / 256, 256>>>(sc4);
    k_scan     <<<1, 1024>>>();
    k_collect  <<<NQ / 256, 256>>>(sc4);
    k_rank     <<<128, 256>>>();
    k_transform<<<8, 256>>>(sc, dl, imi, anc);
    k_mask     <<<dim3(32, 8), 64>>>();
    k_reduceout<<<1, 1024, MASK_ROWS * 32 * sizeof(unsigned long long)>>>(out, out_size);
}